// round 3
// baseline (speedup 1.0000x reference)
#include <cuda_runtime.h>
#include <cuda_bf16.h>
#include <cstdint>

// ---------------- static scratch (no allocations allowed) ----------------
#define MAXN 100000
#define MAXE 3200000
#define MAXG 256

__device__ float g_bufT[(size_t)MAXN * 128];
__device__ float g_bufA[(size_t)MAXN * 128];
__device__ float g_bufB[(size_t)MAXN * 128];
__device__ float g_deg[MAXN];
__device__ float g_dinv[MAXN];
__device__ float g_enorm[MAXE];
__device__ int   g_start[MAXG + 1];
__device__ float g_pooled[MAXG * 64];

// ---------------- degree / norm prep ----------------
__global__ void deg_init_kernel(float* __restrict__ deg, int N) {
    int i = blockIdx.x * blockDim.x + threadIdx.x;
    if (i < N) deg[i] = 1.0f;  // self loop
}

__global__ void deg_accum_kernel(const int* __restrict__ dst, float* __restrict__ deg, int E) {
    int e = blockIdx.x * blockDim.x + threadIdx.x;
    if (e < E) atomicAdd(&deg[dst[e]], 1.0f);
}

__global__ void dinv_kernel(const float* __restrict__ deg, float* __restrict__ dinv, int N) {
    int i = blockIdx.x * blockDim.x + threadIdx.x;
    if (i < N) dinv[i] = rsqrtf(deg[i]);
}

__global__ void enorm_kernel(const int* __restrict__ src, const int* __restrict__ dst,
                             const float* __restrict__ dinv, float* __restrict__ nrm, int E) {
    int e = blockIdx.x * blockDim.x + threadIdx.x;
    if (e < E) nrm[e] = dinv[src[e]] * dinv[dst[e]];
}

// ---------------- GEMM: C[N,DOUT] = act(A)[N,DIN] @ W[DIN,DOUT] ----------------
template <int DIN, int DOUT, bool RELU_IN>
__global__ void gemm_kernel(const float* __restrict__ A, const float* __restrict__ W,
                            float* __restrict__ C, int N) {
    constexpr int TR = 32;         // rows per block
    constexpr int KC = 32;         // k chunk
    constexpr int CT = DOUT / 32;  // cols per thread (4 or 2)
    __shared__ float As[TR][KC + 1];
    __shared__ float Ws[KC][DOUT];
    const int tid = threadIdx.x;  // 128 threads
    const int tx = tid & 31;
    const int ty = tid >> 5;  // 0..3
    const int rbase = blockIdx.x * TR;

    float acc[8][CT];
#pragma unroll
    for (int i = 0; i < 8; i++)
#pragma unroll
        for (int j = 0; j < CT; j++) acc[i][j] = 0.f;

    for (int k0 = 0; k0 < DIN; k0 += KC) {
        // A tile: 32x32, 128 threads x 2 float4
#pragma unroll
        for (int it = 0; it < 2; it++) {
            int r = (tid >> 3) + it * 16;
            int c = (tid & 7) * 4;
            float4 v = make_float4(0.f, 0.f, 0.f, 0.f);
            int gr = rbase + r;
            if (gr < N) v = *(const float4*)(A + (size_t)gr * DIN + k0 + c);
            if (RELU_IN) {
                v.x = fmaxf(v.x, 0.f); v.y = fmaxf(v.y, 0.f);
                v.z = fmaxf(v.z, 0.f); v.w = fmaxf(v.w, 0.f);
            }
            As[r][c + 0] = v.x; As[r][c + 1] = v.y;
            As[r][c + 2] = v.z; As[r][c + 3] = v.w;
        }
        // W tile: KC x DOUT
        constexpr int WLOOP = (KC * DOUT) / (128 * 4);
#pragma unroll
        for (int it = 0; it < WLOOP; it++) {
            int idx = (it * 128 + tid) * 4;
            int kk = idx / DOUT;
            int c = idx % DOUT;
            *(float4*)(&Ws[kk][c]) = *(const float4*)(W + (size_t)(k0 + kk) * DOUT + c);
        }
        __syncthreads();
#pragma unroll
        for (int kk = 0; kk < KC; kk++) {
            float wv[CT];
#pragma unroll
            for (int j = 0; j < CT; j++) wv[j] = Ws[kk][tx * CT + j];
#pragma unroll
            for (int rr = 0; rr < 8; rr++) {
                float a = As[ty * 8 + rr][kk];
#pragma unroll
                for (int j = 0; j < CT; j++) acc[rr][j] = fmaf(a, wv[j], acc[rr][j]);
            }
        }
        __syncthreads();
    }
#pragma unroll
    for (int rr = 0; rr < 8; rr++) {
        int gr = rbase + ty * 8 + rr;
        if (gr < N) {
            if constexpr (CT == 4) {
                *(float4*)(C + (size_t)gr * DOUT + tx * 4) =
                    make_float4(acc[rr][0], acc[rr][1], acc[rr][2], acc[rr][3]);
            } else {
                *(float2*)(C + (size_t)gr * DOUT + tx * 2) =
                    make_float2(acc[rr][0], acc[rr][1]);
            }
        }
    }
}

// ---------------- propagate init: out = dinv^2 * t + bias (self loop folded) ----------------
template <int D>
__global__ void init_out_kernel(const float* __restrict__ t, const float* __restrict__ dinv,
                                const float* __restrict__ bias, float* __restrict__ out, int N) {
    constexpr int VPR = D / 4;  // float4 per row
    long long idx = (long long)blockIdx.x * blockDim.x + threadIdx.x;
    long long total = (long long)N * VPR;
    if (idx >= total) return;
    int i = (int)(idx / VPR);
    int c = (int)(idx % VPR) * 4;
    float dv = dinv[i];
    float sc = dv * dv;
    float4 v = *(const float4*)(t + (size_t)i * D + c);
    float4 b = make_float4(0.f, 0.f, 0.f, 0.f);
    if (bias) b = *(const float4*)(bias + c);
    float4 o;
    o.x = fmaf(sc, v.x, b.x); o.y = fmaf(sc, v.y, b.y);
    o.z = fmaf(sc, v.z, b.z); o.w = fmaf(sc, v.w, b.w);
    *(float4*)(out + (size_t)i * D + c) = o;
}

// ---------------- propagate: out[dst] += norm * t[src]  (vector red.add) ----------------
template <int D>
__global__ void prop_kernel(const float* __restrict__ t, float* __restrict__ out,
                            const int* __restrict__ src, const int* __restrict__ dst,
                            const float* __restrict__ nrm, int E) {
    constexpr int TPE = D / 4;  // threads per edge (16 or 32)
    long long idx = (long long)blockIdx.x * blockDim.x + threadIdx.x;
    int e = (int)(idx / TPE);
    int c = (int)(idx % TPE) * 4;
    if (e >= E) return;
    int s = src[e];
    int d = dst[e];
    float w = nrm[e];
    float4 v = *(const float4*)(t + (size_t)s * D + c);
    v.x *= w; v.y *= w; v.z *= w; v.w *= w;
    float* p = out + (size_t)d * D + c;
    asm volatile("red.global.add.v4.f32 [%0], {%1,%2,%3,%4};"
                 :: "l"(p), "f"(v.x), "f"(v.y), "f"(v.z), "f"(v.w)
                 : "memory");
}

// ---------------- relu in-place ----------------
__global__ void relu_kernel(float* __restrict__ z, long long total4) {
    long long idx = (long long)blockIdx.x * blockDim.x + threadIdx.x;
    if (idx >= total4) return;
    float4 v = *(float4*)(z + idx * 4);
    v.x = fmaxf(v.x, 0.f); v.y = fmaxf(v.y, 0.f);
    v.z = fmaxf(v.z, 0.f); v.w = fmaxf(v.w, 0.f);
    *(float4*)(z + idx * 4) = v;
}

// ---------------- segment starts via binary search on sorted batch (int32) ----------------
__global__ void seg_start_kernel(const int* __restrict__ batch, int N, int G,
                                 int* __restrict__ start) {
    int g = blockIdx.x * blockDim.x + threadIdx.x;
    if (g > G) return;
    int lo = 0, hi = N;
    while (lo < hi) {
        int mid = (lo + hi) >> 1;
        if (batch[mid] < g) lo = mid + 1; else hi = mid;
    }
    start[g] = lo;
}

// ---------------- max pool per graph (+ sg_b folded in) ----------------
__global__ void pool_kernel(const float* __restrict__ z, const int* __restrict__ start,
                            const float* __restrict__ sgb, float* __restrict__ pooled) {
    int g = blockIdx.x;
    int j = threadIdx.x;  // 64
    int s = start[g], e = start[g + 1];
    float m = -3.4028235e38f;
    for (int i = s; i < e; i++) m = fmaxf(m, z[(size_t)i * 64 + j]);
    pooled[g * 64 + j] = m + sgb[j];
}

// ---------------- head MLP ----------------
__global__ void head_kernel(const float* __restrict__ pooled,
                            const float* __restrict__ fc1w, const float* __restrict__ fc1b,
                            const float* __restrict__ fc2w, const float* __restrict__ fc2b,
                            const float* __restrict__ cpdw, const float* __restrict__ cpdb,
                            const float* __restrict__ combw, const float* __restrict__ combb,
                            float* __restrict__ out, int G) {
    int g = blockIdx.x;
    int t = threadIdx.x;  // 64
    __shared__ float z0[64], z1[32], z2[16];
    z0[t] = pooled[g * 64 + t];
    __syncthreads();
    if (t < 32) {
        float s = fc1b[t];
        for (int k = 0; k < 64; k++) s = fmaf(z0[k], fc1w[k * 32 + t], s);
        z1[t] = fmaxf(s, 0.f);
    }
    __syncthreads();
    if (t < 16) {
        float s = fc2b[t];
        for (int k = 0; k < 32; k++) s = fmaf(z1[k], fc2w[k * 16 + t], s);
        z2[t] = fmaxf(s, 0.f);
    }
    __syncthreads();
    if (t == 0) {
        float s = cpdb[0];
        for (int k = 0; k < 16; k++) s = fmaf(z2[k], cpdw[k], s);
        out[g] = s;
    }
    if (t == 1) {
        float s = combb[0];
        for (int k = 0; k < 16; k++) s = fmaf(z2[k], combw[k], s);
        out[G + g] = s;
    }
}

// ---------------- host side ----------------
static inline int cdiv(long long a, int b) { return (int)((a + b - 1) / b); }

extern "C" void kernel_launch(void* const* d_in, const int* in_sizes, int n_in,
                              void* d_out, int out_size) {
    const float* x     = (const float*)d_in[0];
    const int*   ei    = (const int*)d_in[1];    // int32 (JAX x64 disabled)
    const int*   batch = (const int*)d_in[2];    // int32
    const float* enc_w1 = (const float*)d_in[3];
    const float* enc_b1 = (const float*)d_in[4];
    const float* enc_w2 = (const float*)d_in[5];
    const float* enc_b2 = (const float*)d_in[6];
    const float* w1 = (const float*)d_in[7];
    const float* b1 = (const float*)d_in[8];
    const float* w2 = (const float*)d_in[9];
    const float* b2 = (const float*)d_in[10];
    const float* w3 = (const float*)d_in[11];
    const float* b3 = (const float*)d_in[12];
    const float* sg_w = (const float*)d_in[13];
    const float* sg_b = (const float*)d_in[14];
    const float* fc1_w = (const float*)d_in[15];
    const float* fc1_b = (const float*)d_in[16];
    const float* fc2_w = (const float*)d_in[17];
    const float* fc2_b = (const float*)d_in[18];
    const float* cpd_w = (const float*)d_in[19];
    const float* cpd_b = (const float*)d_in[20];
    const float* comb_w = (const float*)d_in[21];
    const float* comb_b = (const float*)d_in[22];
    float* out = (float*)d_out;

    const int N = in_sizes[0] / 128;
    const int E = in_sizes[1] / 2;
    const int G = out_size / 2;

    const int* src = ei;       // edge_index[0]
    const int* dst = ei + E;   // edge_index[1]

    void *pT, *pA, *pB, *pDeg, *pDinv, *pNrm, *pStart, *pPool;
    cudaGetSymbolAddress(&pT, g_bufT);
    cudaGetSymbolAddress(&pA, g_bufA);
    cudaGetSymbolAddress(&pB, g_bufB);
    cudaGetSymbolAddress(&pDeg, g_deg);
    cudaGetSymbolAddress(&pDinv, g_dinv);
    cudaGetSymbolAddress(&pNrm, g_enorm);
    cudaGetSymbolAddress(&pStart, g_start);
    cudaGetSymbolAddress(&pPool, g_pooled);
    float* bufT = (float*)pT;
    float* bufA = (float*)pA;
    float* bufB = (float*)pB;
    float* deg = (float*)pDeg;
    float* dinv = (float*)pDinv;
    float* nrm = (float*)pNrm;
    int* start = (int*)pStart;
    float* pooled = (float*)pPool;

    const int TB = 256;

    // ---- degree / norm prep ----
    deg_init_kernel<<<cdiv(N, TB), TB>>>(deg, N);
    deg_accum_kernel<<<cdiv(E, TB), TB>>>(dst, deg, E);
    dinv_kernel<<<cdiv(N, TB), TB>>>(deg, dinv, N);
    enorm_kernel<<<cdiv(E, TB), TB>>>(src, dst, dinv, nrm, E);

    const int gemmB = 128;
    const int gemmGrid = cdiv(N, 32);
    const long long p64 = (long long)E * 16;
    const long long p128 = (long long)E * 32;
    const long long n64v4 = (long long)N * 16;   // N*64/4
    const long long n128v4 = (long long)N * 32;  // N*128/4

    // ---- encoder layer 1: relu(prop(x@W)+b) (relu fused into next GEMM) ----
    gemm_kernel<128, 128, false><<<gemmGrid, gemmB>>>(x, enc_w1, bufT, N);
    init_out_kernel<128><<<cdiv(n128v4, TB), TB>>>(bufT, dinv, enc_b1, bufA, N);
    prop_kernel<128><<<cdiv(p128, TB), TB>>>(bufT, bufA, src, dst, nrm, E);

    // ---- encoder layer 2: prop(relu(h)@W)+b (no relu after) ----
    gemm_kernel<128, 64, true><<<gemmGrid, gemmB>>>(bufA, enc_w2, bufT, N);
    init_out_kernel<64><<<cdiv(n64v4, TB), TB>>>(bufT, dinv, enc_b2, bufB, N);
    prop_kernel<64><<<cdiv(p64, TB), TB>>>(bufT, bufB, src, dst, nrm, E);

    // ---- conv1 (input NOT relu'd) ----
    gemm_kernel<64, 64, false><<<gemmGrid, gemmB>>>(bufB, w1, bufT, N);
    init_out_kernel<64><<<cdiv(n64v4, TB), TB>>>(bufT, dinv, b1, bufA, N);
    prop_kernel<64><<<cdiv(p64, TB), TB>>>(bufT, bufA, src, dst, nrm, E);

    // ---- conv2 (relu fused on input) ----
    gemm_kernel<64, 64, true><<<gemmGrid, gemmB>>>(bufA, w2, bufT, N);
    init_out_kernel<64><<<cdiv(n64v4, TB), TB>>>(bufT, dinv, b2, bufB, N);
    prop_kernel<64><<<cdiv(p64, TB), TB>>>(bufT, bufB, src, dst, nrm, E);

    // ---- conv3 (relu fused on input), explicit relu after (SG reads it raw) ----
    gemm_kernel<64, 64, true><<<gemmGrid, gemmB>>>(bufB, w3, bufT, N);
    init_out_kernel<64><<<cdiv(n64v4, TB), TB>>>(bufT, dinv, b3, bufA, N);
    prop_kernel<64><<<cdiv(p64, TB), TB>>>(bufT, bufA, src, dst, nrm, E);
    relu_kernel<<<cdiv(n64v4, TB), TB>>>(bufA, n64v4);

    // ---- SGConv: 4 propagations ----
    init_out_kernel<64><<<cdiv(n64v4, TB), TB>>>(bufA, dinv, nullptr, bufB, N);
    prop_kernel<64><<<cdiv(p64, TB), TB>>>(bufA, bufB, src, dst, nrm, E);
    init_out_kernel<64><<<cdiv(n64v4, TB), TB>>>(bufB, dinv, nullptr, bufA, N);
    prop_kernel<64><<<cdiv(p64, TB), TB>>>(bufB, bufA, src, dst, nrm, E);
    init_out_kernel<64><<<cdiv(n64v4, TB), TB>>>(bufA, dinv, nullptr, bufB, N);
    prop_kernel<64><<<cdiv(p64, TB), TB>>>(bufA, bufB, src, dst, nrm, E);
    init_out_kernel<64><<<cdiv(n64v4, TB), TB>>>(bufB, dinv, nullptr, bufA, N);
    prop_kernel<64><<<cdiv(p64, TB), TB>>>(bufB, bufA, src, dst, nrm, E);

    // ---- SG linear (bias folded past max-pool) ----
    gemm_kernel<64, 64, false><<<gemmGrid, gemmB>>>(bufA, sg_w, bufB, N);

    // ---- pool + head ----
    seg_start_kernel<<<cdiv(G + 1, TB), TB>>>(batch, N, G, start);
    pool_kernel<<<G, 64>>>(bufB, start, sg_b, pooled);
    head_kernel<<<G, 64>>>(pooled, fc1_w, fc1_b, fc2_w, fc2_b,
                           cpd_w, cpd_b, comb_w, comb_b, out, G);
}

// round 4
// speedup vs baseline: 2.1884x; 2.1884x over previous
#include <cuda_runtime.h>
#include <cuda_bf16.h>
#include <cstdint>

// ---------------- static scratch (no allocations allowed) ----------------
#define MAXN 100000
#define MAXE 3200000
#define MAXG 256

__device__ float g_bufT[(size_t)MAXN * 128];
__device__ float g_bufA[(size_t)MAXN * 128];
__device__ float g_bufB[(size_t)MAXN * 128];
__device__ float g_deg[MAXN];
__device__ float g_dinv[MAXN];
__device__ int   g_rowptr[MAXN + 1];
__device__ int   g_tmp[MAXN];
__device__ int   g_sums[256];
__device__ int   g_fill[MAXN];
__device__ int2  g_pairs[MAXE];       // (src, norm-as-int)
__device__ int   g_start[MAXG + 1];
__device__ float g_pooled[MAXG * 64];

static inline int cdiv(long long a, int b) { return (int)((a + b - 1) / b); }

// ---------------- degree / norm prep ----------------
__global__ void deg_init_kernel(float* __restrict__ deg, int* __restrict__ fill, int N) {
    int i = blockIdx.x * blockDim.x + threadIdx.x;
    if (i < N) { deg[i] = 1.0f; fill[i] = 0; }  // self loop
}

__global__ void deg_accum_kernel(const int* __restrict__ dst, float* __restrict__ deg, int E) {
    int e = blockIdx.x * blockDim.x + threadIdx.x;
    if (e < E) atomicAdd(&deg[dst[e]], 1.0f);
}

__global__ void dinv_kernel(const float* __restrict__ deg, float* __restrict__ dinv, int N) {
    int i = blockIdx.x * blockDim.x + threadIdx.x;
    if (i < N) dinv[i] = rsqrtf(deg[i]);
}

// ---------------- CSR build: scan of in-degree (excl self loops) ----------------
__global__ void scan_chunk_kernel(const float* __restrict__ deg, int* __restrict__ excl,
                                  int* __restrict__ sums, int N) {
    __shared__ int sh[1024];
    int i = blockIdx.x * 1024 + threadIdx.x;
    int v = 0;
    if (i < N) v = (int)deg[i] - 1;  // deg includes self loop
    sh[threadIdx.x] = v;
    __syncthreads();
    for (int off = 1; off < 1024; off <<= 1) {
        int add = (threadIdx.x >= off) ? sh[threadIdx.x - off] : 0;
        __syncthreads();
        sh[threadIdx.x] += add;
        __syncthreads();
    }
    if (i < N) excl[i] = sh[threadIdx.x] - v;  // exclusive within chunk
    if (threadIdx.x == 1023) sums[blockIdx.x] = sh[1023];
}

__global__ void scan_sums_kernel(int* __restrict__ sums, int nchunks) {
    if (threadIdx.x == 0 && blockIdx.x == 0) {
        int run = 0;
        for (int c = 0; c < nchunks; c++) {
            int v = sums[c];
            sums[c] = run;
            run += v;
        }
    }
}

__global__ void finalize_rowptr_kernel(const int* __restrict__ excl, const int* __restrict__ sums,
                                       int* __restrict__ rp, int N, int E) {
    int i = blockIdx.x * blockDim.x + threadIdx.x;
    if (i < N) rp[i] = excl[i] + sums[i >> 10];
    if (i == 0) rp[N] = E;
}

__global__ void scatter_kernel(const int* __restrict__ src, const int* __restrict__ dst,
                               const float* __restrict__ dinv, const int* __restrict__ rp,
                               int* __restrict__ fill, int2* __restrict__ pairs, int E) {
    int e = blockIdx.x * blockDim.x + threadIdx.x;
    if (e >= E) return;
    int s = src[e];
    int d = dst[e];
    int pos = rp[d] + atomicAdd(&fill[d], 1);
    pairs[pos] = make_int2(s, __float_as_int(dinv[s] * dinv[d]));
}

// ---------------- GEMM: C[N,DOUT] = act(A)[N,DIN] @ W[DIN,DOUT] ----------------
template <int DIN, int DOUT, bool RELU_IN>
__global__ void gemm_kernel(const float* __restrict__ A, const float* __restrict__ W,
                            float* __restrict__ C, int N) {
    constexpr int TR = 32;
    constexpr int KC = 32;
    constexpr int CT = DOUT / 32;
    __shared__ float As[TR][KC + 1];
    __shared__ float Ws[KC][DOUT];
    const int tid = threadIdx.x;  // 128
    const int tx = tid & 31;
    const int ty = tid >> 5;
    const int rbase = blockIdx.x * TR;

    float acc[8][CT];
#pragma unroll
    for (int i = 0; i < 8; i++)
#pragma unroll
        for (int j = 0; j < CT; j++) acc[i][j] = 0.f;

    for (int k0 = 0; k0 < DIN; k0 += KC) {
#pragma unroll
        for (int it = 0; it < 2; it++) {
            int r = (tid >> 3) + it * 16;
            int c = (tid & 7) * 4;
            float4 v = make_float4(0.f, 0.f, 0.f, 0.f);
            int gr = rbase + r;
            if (gr < N) v = *(const float4*)(A + (size_t)gr * DIN + k0 + c);
            if (RELU_IN) {
                v.x = fmaxf(v.x, 0.f); v.y = fmaxf(v.y, 0.f);
                v.z = fmaxf(v.z, 0.f); v.w = fmaxf(v.w, 0.f);
            }
            As[r][c + 0] = v.x; As[r][c + 1] = v.y;
            As[r][c + 2] = v.z; As[r][c + 3] = v.w;
        }
        constexpr int WLOOP = (KC * DOUT) / (128 * 4);
#pragma unroll
        for (int it = 0; it < WLOOP; it++) {
            int idx = (it * 128 + tid) * 4;
            int kk = idx / DOUT;
            int c = idx % DOUT;
            *(float4*)(&Ws[kk][c]) = *(const float4*)(W + (size_t)(k0 + kk) * DOUT + c);
        }
        __syncthreads();
#pragma unroll
        for (int kk = 0; kk < KC; kk++) {
            float wv[CT];
#pragma unroll
            for (int j = 0; j < CT; j++) wv[j] = Ws[kk][tx * CT + j];
#pragma unroll
            for (int rr = 0; rr < 8; rr++) {
                float a = As[ty * 8 + rr][kk];
#pragma unroll
                for (int j = 0; j < CT; j++) acc[rr][j] = fmaf(a, wv[j], acc[rr][j]);
            }
        }
        __syncthreads();
    }
#pragma unroll
    for (int rr = 0; rr < 8; rr++) {
        int gr = rbase + ty * 8 + rr;
        if (gr < N) {
            if constexpr (CT == 4) {
                *(float4*)(C + (size_t)gr * DOUT + tx * 4) =
                    make_float4(acc[rr][0], acc[rr][1], acc[rr][2], acc[rr][3]);
            } else {
                *(float2*)(C + (size_t)gr * DOUT + tx * 2) =
                    make_float2(acc[rr][0], acc[rr][1]);
            }
        }
    }
}

// ---------------- CSR propagate: out[i] = dinv[i]^2*act(t[i]) + b + sum_j w_j*act(t[src_j]) ----
template <int VT> struct VecT;
template <> struct VecT<2> { using T = float2; };
template <> struct VecT<4> { using T = float4; };

template <int D, bool RELU>
__global__ void csr_prop_kernel(const float* __restrict__ t, float* __restrict__ out,
                                const int2* __restrict__ pairs, const int* __restrict__ rp,
                                const float* __restrict__ dinv, const float* __restrict__ bias,
                                int N) {
    constexpr int VT = D / 32;
    using V = typename VecT<VT>::T;
    int warp = (blockIdx.x * blockDim.x + threadIdx.x) >> 5;
    int lane = threadIdx.x & 31;
    if (warp >= N) return;
    const int i = warp;
    const int base = lane * VT;
    int j0 = rp[i], j1 = rp[i + 1];

    float acc[VT];
#pragma unroll
    for (int v = 0; v < VT; v++) acc[v] = 0.f;

    int j = j0;
    for (; j + 1 < j1; j += 2) {
        int2 p0 = pairs[j];
        int2 p1 = pairs[j + 1];
        float w0 = __int_as_float(p0.y);
        float w1 = __int_as_float(p1.y);
        float a0[VT], a1[VT];
        *(V*)a0 = *(const V*)(t + (size_t)p0.x * D + base);
        *(V*)a1 = *(const V*)(t + (size_t)p1.x * D + base);
#pragma unroll
        for (int v = 0; v < VT; v++) {
            float x0 = RELU ? fmaxf(a0[v], 0.f) : a0[v];
            float x1 = RELU ? fmaxf(a1[v], 0.f) : a1[v];
            acc[v] = fmaf(w0, x0, acc[v]);
            acc[v] = fmaf(w1, x1, acc[v]);
        }
    }
    if (j < j1) {
        int2 p0 = pairs[j];
        float w0 = __int_as_float(p0.y);
        float a0[VT];
        *(V*)a0 = *(const V*)(t + (size_t)p0.x * D + base);
#pragma unroll
        for (int v = 0; v < VT; v++) {
            float x0 = RELU ? fmaxf(a0[v], 0.f) : a0[v];
            acc[v] = fmaf(w0, x0, acc[v]);
        }
    }

    float dv = dinv[i];
    float sc = dv * dv;
    float self[VT];
    *(V*)self = *(const V*)(t + (size_t)i * D + base);
    float o[VT];
#pragma unroll
    for (int v = 0; v < VT; v++) {
        float sv = RELU ? fmaxf(self[v], 0.f) : self[v];
        float b = bias ? bias[base + v] : 0.f;
        o[v] = fmaf(sc, sv, acc[v]) + b;
    }
    *(V*)(out + (size_t)i * D + base) = *(const V*)o;
}

// ---------------- segment starts via binary search on sorted batch (int32) ----------------
__global__ void seg_start_kernel(const int* __restrict__ batch, int N, int G,
                                 int* __restrict__ start) {
    int g = blockIdx.x * blockDim.x + threadIdx.x;
    if (g > G) return;
    int lo = 0, hi = N;
    while (lo < hi) {
        int mid = (lo + hi) >> 1;
        if (batch[mid] < g) lo = mid + 1; else hi = mid;
    }
    start[g] = lo;
}

// ---------------- max pool per graph (+ sg_b folded in) ----------------
__global__ void pool_kernel(const float* __restrict__ z, const int* __restrict__ start,
                            const float* __restrict__ sgb, float* __restrict__ pooled) {
    int g = blockIdx.x;
    int j = threadIdx.x;  // 64
    int s = start[g], e = start[g + 1];
    float m = -3.4028235e38f;
    for (int i = s; i < e; i++) m = fmaxf(m, z[(size_t)i * 64 + j]);
    pooled[g * 64 + j] = m + sgb[j];
}

// ---------------- head MLP ----------------
__global__ void head_kernel(const float* __restrict__ pooled,
                            const float* __restrict__ fc1w, const float* __restrict__ fc1b,
                            const float* __restrict__ fc2w, const float* __restrict__ fc2b,
                            const float* __restrict__ cpdw, const float* __restrict__ cpdb,
                            const float* __restrict__ combw, const float* __restrict__ combb,
                            float* __restrict__ out, int G) {
    int g = blockIdx.x;
    int t = threadIdx.x;  // 64
    __shared__ float z0[64], z1[32], z2[16];
    z0[t] = pooled[g * 64 + t];
    __syncthreads();
    if (t < 32) {
        float s = fc1b[t];
        for (int k = 0; k < 64; k++) s = fmaf(z0[k], fc1w[k * 32 + t], s);
        z1[t] = fmaxf(s, 0.f);
    }
    __syncthreads();
    if (t < 16) {
        float s = fc2b[t];
        for (int k = 0; k < 32; k++) s = fmaf(z1[k], fc2w[k * 16 + t], s);
        z2[t] = fmaxf(s, 0.f);
    }
    __syncthreads();
    if (t == 0) {
        float s = cpdb[0];
        for (int k = 0; k < 16; k++) s = fmaf(z2[k], cpdw[k], s);
        out[g] = s;
    }
    if (t == 1) {
        float s = combb[0];
        for (int k = 0; k < 16; k++) s = fmaf(z2[k], combw[k], s);
        out[G + g] = s;
    }
}

// ---------------- host side ----------------
extern "C" void kernel_launch(void* const* d_in, const int* in_sizes, int n_in,
                              void* d_out, int out_size) {
    const float* x     = (const float*)d_in[0];
    const int*   ei    = (const int*)d_in[1];  // int32 (JAX x64 disabled)
    const int*   batch = (const int*)d_in[2];  // int32
    const float* enc_w1 = (const float*)d_in[3];
    const float* enc_b1 = (const float*)d_in[4];
    const float* enc_w2 = (const float*)d_in[5];
    const float* enc_b2 = (const float*)d_in[6];
    const float* w1 = (const float*)d_in[7];
    const float* b1 = (const float*)d_in[8];
    const float* w2 = (const float*)d_in[9];
    const float* b2 = (const float*)d_in[10];
    const float* w3 = (const float*)d_in[11];
    const float* b3 = (const float*)d_in[12];
    const float* sg_w = (const float*)d_in[13];
    const float* sg_b = (const float*)d_in[14];
    const float* fc1_w = (const float*)d_in[15];
    const float* fc1_b = (const float*)d_in[16];
    const float* fc2_w = (const float*)d_in[17];
    const float* fc2_b = (const float*)d_in[18];
    const float* cpd_w = (const float*)d_in[19];
    const float* cpd_b = (const float*)d_in[20];
    const float* comb_w = (const float*)d_in[21];
    const float* comb_b = (const float*)d_in[22];
    float* out = (float*)d_out;

    const int N = in_sizes[0] / 128;
    const int E = in_sizes[1] / 2;
    const int G = out_size / 2;

    const int* src = ei;
    const int* dst = ei + E;

    void *pT, *pA, *pB, *pDeg, *pDinv, *pRp, *pTmp, *pSums, *pFill, *pPairs, *pStart, *pPool;
    cudaGetSymbolAddress(&pT, g_bufT);
    cudaGetSymbolAddress(&pA, g_bufA);
    cudaGetSymbolAddress(&pB, g_bufB);
    cudaGetSymbolAddress(&pDeg, g_deg);
    cudaGetSymbolAddress(&pDinv, g_dinv);
    cudaGetSymbolAddress(&pRp, g_rowptr);
    cudaGetSymbolAddress(&pTmp, g_tmp);
    cudaGetSymbolAddress(&pSums, g_sums);
    cudaGetSymbolAddress(&pFill, g_fill);
    cudaGetSymbolAddress(&pPairs, g_pairs);
    cudaGetSymbolAddress(&pStart, g_start);
    cudaGetSymbolAddress(&pPool, g_pooled);
    float* bufT = (float*)pT;
    float* bufA = (float*)pA;
    float* bufB = (float*)pB;
    float* deg = (float*)pDeg;
    float* dinv = (float*)pDinv;
    int* rp = (int*)pRp;
    int* tmp = (int*)pTmp;
    int* sums = (int*)pSums;
    int* fill = (int*)pFill;
    int2* pairs = (int2*)pPairs;
    int* start = (int*)pStart;
    float* pooled = (float*)pPool;

    const int TB = 256;
    const int nchunks = cdiv(N, 1024);

    // ---- degree / dinv ----
    deg_init_kernel<<<cdiv(N, TB), TB>>>(deg, fill, N);
    deg_accum_kernel<<<cdiv(E, TB), TB>>>(dst, deg, E);
    dinv_kernel<<<cdiv(N, TB), TB>>>(deg, dinv, N);

    // ---- CSR build (counting sort by dst) ----
    scan_chunk_kernel<<<nchunks, 1024>>>(deg, tmp, sums, N);
    scan_sums_kernel<<<1, 32>>>(sums, nchunks);
    finalize_rowptr_kernel<<<cdiv(N, TB), TB>>>(tmp, sums, rp, N, E);
    scatter_kernel<<<cdiv(E, TB), TB>>>(src, dst, dinv, rp, fill, pairs, E);

    const int gemmB = 128;
    const int gemmGrid = cdiv(N, 32);
    const int propGrid = cdiv(N, 8);  // 8 warps/block, warp per node

    // ---- encoder layer 1: relu fused into next GEMM ----
    gemm_kernel<128, 128, false><<<gemmGrid, gemmB>>>(x, enc_w1, bufT, N);
    csr_prop_kernel<128, false><<<propGrid, TB>>>(bufT, bufA, pairs, rp, dinv, enc_b1, N);

    // ---- encoder layer 2 ----
    gemm_kernel<128, 64, true><<<gemmGrid, gemmB>>>(bufA, enc_w2, bufT, N);
    csr_prop_kernel<64, false><<<propGrid, TB>>>(bufT, bufB, pairs, rp, dinv, enc_b2, N);

    // ---- conv1 ----
    gemm_kernel<64, 64, false><<<gemmGrid, gemmB>>>(bufB, w1, bufT, N);
    csr_prop_kernel<64, false><<<propGrid, TB>>>(bufT, bufA, pairs, rp, dinv, b1, N);

    // ---- conv2 ----
    gemm_kernel<64, 64, true><<<gemmGrid, gemmB>>>(bufA, w2, bufT, N);
    csr_prop_kernel<64, false><<<propGrid, TB>>>(bufT, bufB, pairs, rp, dinv, b2, N);

    // ---- conv3 (output bufA = pre-relu) ----
    gemm_kernel<64, 64, true><<<gemmGrid, gemmB>>>(bufB, w3, bufT, N);
    csr_prop_kernel<64, false><<<propGrid, TB>>>(bufT, bufA, pairs, rp, dinv, b3, N);

    // ---- SGConv: 4 props (relu of conv3 fused into prop 1's loads) ----
    csr_prop_kernel<64, true><<<propGrid, TB>>>(bufA, bufB, pairs, rp, dinv, nullptr, N);
    csr_prop_kernel<64, false><<<propGrid, TB>>>(bufB, bufA, pairs, rp, dinv, nullptr, N);
    csr_prop_kernel<64, false><<<propGrid, TB>>>(bufA, bufB, pairs, rp, dinv, nullptr, N);
    csr_prop_kernel<64, false><<<propGrid, TB>>>(bufB, bufA, pairs, rp, dinv, nullptr, N);

    // ---- SG linear (bias folded past max-pool) ----
    gemm_kernel<64, 64, false><<<gemmGrid, gemmB>>>(bufA, sg_w, bufB, N);

    // ---- pool + head ----
    seg_start_kernel<<<cdiv(G + 1, TB), TB>>>(batch, N, G, start);
    pool_kernel<<<G, 64>>>(bufB, start, sg_b, pooled);
    head_kernel<<<G, 64>>>(pooled, fc1_w, fc1_b, fc2_w, fc2_b,
                           cpd_w, cpd_b, comb_w, comb_b, out, G);
}

// round 5
// speedup vs baseline: 2.5984x; 1.1874x over previous
#include <cuda_runtime.h>
#include <cuda_fp16.h>
#include <cstdint>

// ---------------- static scratch (no allocations allowed) ----------------
#define MAXN 100000
#define MAXE 3200000
#define MAXG 256

__device__ __half g_h16T[(size_t)MAXN * 128];  // gathered GEMM outputs (fp16)
__device__ __half g_h16X[(size_t)MAXN * 64];   // SG chain ping
__device__ __half g_h16Y[(size_t)MAXN * 64];   // SG chain pong
__device__ float  g_bufA[(size_t)MAXN * 128];  // prop outputs (fp32, read linearly)
__device__ float  g_bufB[(size_t)MAXN * 64];   // SG linear out (fp32, pooled)
__device__ float  g_deg[MAXN];
__device__ float  g_dinv[MAXN];
__device__ int    g_rowptr[MAXN + 1];
__device__ int    g_tmp[MAXN];
__device__ int    g_sums[256];
__device__ int    g_fill[MAXN];
__device__ int2   g_pairs[MAXE];  // (src, norm-as-int)
__device__ int    g_start[MAXG + 1];
__device__ float  g_pooled[MAXG * 64];

static inline int cdiv(long long a, int b) { return (int)((a + b - 1) / b); }

// ---------------- degree / norm prep ----------------
__global__ void deg_init_kernel(float* __restrict__ deg, int* __restrict__ fill, int N) {
    int i = blockIdx.x * blockDim.x + threadIdx.x;
    if (i < N) { deg[i] = 1.0f; fill[i] = 0; }  // self loop
}

__global__ void deg_accum_kernel(const int* __restrict__ dst, float* __restrict__ deg, int E) {
    int e = blockIdx.x * blockDim.x + threadIdx.x;
    if (e < E) atomicAdd(&deg[dst[e]], 1.0f);
}

__global__ void dinv_kernel(const float* __restrict__ deg, float* __restrict__ dinv, int N) {
    int i = blockIdx.x * blockDim.x + threadIdx.x;
    if (i < N) dinv[i] = rsqrtf(deg[i]);
}

// ---------------- CSR build: scan of in-degree (excl self loops) ----------------
__global__ void scan_chunk_kernel(const float* __restrict__ deg, int* __restrict__ excl,
                                  int* __restrict__ sums, int N) {
    __shared__ int sh[1024];
    int i = blockIdx.x * 1024 + threadIdx.x;
    int v = 0;
    if (i < N) v = (int)deg[i] - 1;
    sh[threadIdx.x] = v;
    __syncthreads();
    for (int off = 1; off < 1024; off <<= 1) {
        int add = (threadIdx.x >= off) ? sh[threadIdx.x - off] : 0;
        __syncthreads();
        sh[threadIdx.x] += add;
        __syncthreads();
    }
    if (i < N) excl[i] = sh[threadIdx.x] - v;
    if (threadIdx.x == 1023) sums[blockIdx.x] = sh[1023];
}

__global__ void scan_sums_kernel(int* __restrict__ sums, int nchunks) {
    if (threadIdx.x == 0 && blockIdx.x == 0) {
        int run = 0;
        for (int c = 0; c < nchunks; c++) {
            int v = sums[c];
            sums[c] = run;
            run += v;
        }
    }
}

__global__ void finalize_rowptr_kernel(const int* __restrict__ excl, const int* __restrict__ sums,
                                       int* __restrict__ rp, int N, int E) {
    int i = blockIdx.x * blockDim.x + threadIdx.x;
    if (i < N) rp[i] = excl[i] + sums[i >> 10];
    if (i == 0) rp[N] = E;
}

__global__ void scatter_kernel(const int* __restrict__ src, const int* __restrict__ dst,
                               const float* __restrict__ dinv, const int* __restrict__ rp,
                               int* __restrict__ fill, int2* __restrict__ pairs, int E) {
    int e = blockIdx.x * blockDim.x + threadIdx.x;
    if (e >= E) return;
    int s = src[e];
    int d = dst[e];
    int pos = rp[d] + atomicAdd(&fill[d], 1);
    pairs[pos] = make_int2(s, __float_as_int(dinv[s] * dinv[d]));
}

// ---------------- GEMM: OUT[N,DOUT] = act(A)[N,DIN] @ W[DIN,DOUT], fp32 math ----------------
template <int DIN, int DOUT, bool RELU_IN, bool OUT_HALF>
__global__ void gemm_kernel(const float* __restrict__ A, const float* __restrict__ W,
                            void* __restrict__ outv, int N) {
    constexpr int TR = 32;
    constexpr int KC = 32;
    constexpr int CT = DOUT / 32;  // 4 or 2
    __shared__ float As[TR][KC + 1];
    __shared__ float Ws[KC][DOUT];
    const int tid = threadIdx.x;  // 128
    const int tx = tid & 31;
    const int ty = tid >> 5;
    const int rbase = blockIdx.x * TR;

    float acc[8][CT];
#pragma unroll
    for (int i = 0; i < 8; i++)
#pragma unroll
        for (int j = 0; j < CT; j++) acc[i][j] = 0.f;

    for (int k0 = 0; k0 < DIN; k0 += KC) {
#pragma unroll
        for (int it = 0; it < 2; it++) {
            int r = (tid >> 3) + it * 16;
            int c = (tid & 7) * 4;
            float4 v = make_float4(0.f, 0.f, 0.f, 0.f);
            int gr = rbase + r;
            if (gr < N) v = *(const float4*)(A + (size_t)gr * DIN + k0 + c);
            if (RELU_IN) {
                v.x = fmaxf(v.x, 0.f); v.y = fmaxf(v.y, 0.f);
                v.z = fmaxf(v.z, 0.f); v.w = fmaxf(v.w, 0.f);
            }
            As[r][c + 0] = v.x; As[r][c + 1] = v.y;
            As[r][c + 2] = v.z; As[r][c + 3] = v.w;
        }
        constexpr int WLOOP = (KC * DOUT) / (128 * 4);
#pragma unroll
        for (int it = 0; it < WLOOP; it++) {
            int idx = (it * 128 + tid) * 4;
            int kk = idx / DOUT;
            int c = idx % DOUT;
            *(float4*)(&Ws[kk][c]) = *(const float4*)(W + (size_t)(k0 + kk) * DOUT + c);
        }
        __syncthreads();
#pragma unroll
        for (int kk = 0; kk < KC; kk++) {
            float wv[CT];
#pragma unroll
            for (int j = 0; j < CT; j++) wv[j] = Ws[kk][tx * CT + j];
#pragma unroll
            for (int rr = 0; rr < 8; rr++) {
                float a = As[ty * 8 + rr][kk];
#pragma unroll
                for (int j = 0; j < CT; j++) acc[rr][j] = fmaf(a, wv[j], acc[rr][j]);
            }
        }
        __syncthreads();
    }
#pragma unroll
    for (int rr = 0; rr < 8; rr++) {
        int gr = rbase + ty * 8 + rr;
        if (gr >= N) continue;
        if constexpr (OUT_HALF) {
            __half* out = (__half*)outv;
            __half2* p = (__half2*)(out + (size_t)gr * DOUT + tx * CT);
#pragma unroll
            for (int j = 0; j < CT / 2; j++)
                p[j] = __floats2half2_rn(acc[rr][2 * j], acc[rr][2 * j + 1]);
        } else {
            float* out = (float*)outv;
            if constexpr (CT == 4) {
                *(float4*)(out + (size_t)gr * DOUT + tx * 4) =
                    make_float4(acc[rr][0], acc[rr][1], acc[rr][2], acc[rr][3]);
            } else {
                *(float2*)(out + (size_t)gr * DOUT + tx * 2) =
                    make_float2(acc[rr][0], acc[rr][1]);
            }
        }
    }
}

// ---------------- CSR propagate, fp16 gather / fp32 accumulate ----------------
// out[i] = dinv[i]^2 * act(t[i]) + bias + sum_j norm_j * act(t[src_j])
template <int D, bool RELU, bool OUT_HALF>
__global__ void csr_prop16_kernel(const __half* __restrict__ t, void* __restrict__ outv,
                                  const int2* __restrict__ pairs, const int* __restrict__ rp,
                                  const float* __restrict__ dinv, const float* __restrict__ bias,
                                  int N) {
    constexpr int H = D / 32;  // halves per lane: 2 (D=64) or 4 (D=128)
    int warp = (blockIdx.x * blockDim.x + threadIdx.x) >> 5;
    int lane = threadIdx.x & 31;
    if (warp >= N) return;
    const int i = warp;
    int j0 = rp[i], j1 = rp[i + 1];

    float acc[H];
#pragma unroll
    for (int v = 0; v < H; v++) acc[v] = 0.f;

    auto load_row = [&](int s, float* f) {
        if constexpr (H == 2) {
            unsigned u = *((const unsigned*)(t + (size_t)s * D) + lane);
            __half2 h = *(__half2*)&u;
            float2 fv = __half22float2(h);
            f[0] = fv.x; f[1] = fv.y;
        } else {
            uint2 u = *((const uint2*)(t + (size_t)s * D) + lane);
            __half2 ha = *(__half2*)&u.x;
            __half2 hb = *(__half2*)&u.y;
            float2 fa = __half22float2(ha);
            float2 fb = __half22float2(hb);
            f[0] = fa.x; f[1] = fa.y; f[2] = fb.x; f[3] = fb.y;
        }
    };

    int j = j0;
    for (; j + 1 < j1; j += 2) {
        int2 p0 = pairs[j];
        int2 p1 = pairs[j + 1];
        float w0 = __int_as_float(p0.y);
        float w1 = __int_as_float(p1.y);
        float a0[H], a1[H];
        load_row(p0.x, a0);
        load_row(p1.x, a1);
#pragma unroll
        for (int v = 0; v < H; v++) {
            float x0 = RELU ? fmaxf(a0[v], 0.f) : a0[v];
            float x1 = RELU ? fmaxf(a1[v], 0.f) : a1[v];
            acc[v] = fmaf(w0, x0, acc[v]);
            acc[v] = fmaf(w1, x1, acc[v]);
        }
    }
    if (j < j1) {
        int2 p0 = pairs[j];
        float w0 = __int_as_float(p0.y);
        float a0[H];
        load_row(p0.x, a0);
#pragma unroll
        for (int v = 0; v < H; v++) {
            float x0 = RELU ? fmaxf(a0[v], 0.f) : a0[v];
            acc[v] = fmaf(w0, x0, acc[v]);
        }
    }

    float dv = dinv[i];
    float sc = dv * dv;
    float self[H];
    load_row(i, self);
    float o[H];
#pragma unroll
    for (int v = 0; v < H; v++) {
        float sv = RELU ? fmaxf(self[v], 0.f) : self[v];
        float b = bias ? bias[lane * H + v] : 0.f;
        o[v] = fmaf(sc, sv, acc[v]) + b;
    }

    if constexpr (OUT_HALF) {
        __half* out = (__half*)outv;
        if constexpr (H == 2) {
            __half2 h = __floats2half2_rn(o[0], o[1]);
            *((unsigned*)(out + (size_t)i * D) + lane) = *(unsigned*)&h;
        } else {
            __half2 ha = __floats2half2_rn(o[0], o[1]);
            __half2 hb = __floats2half2_rn(o[2], o[3]);
            uint2 u;
            u.x = *(unsigned*)&ha;
            u.y = *(unsigned*)&hb;
            *((uint2*)(out + (size_t)i * D) + lane) = u;
        }
    } else {
        float* out = (float*)outv;
        if constexpr (H == 2) {
            *(float2*)(out + (size_t)i * D + lane * 2) = make_float2(o[0], o[1]);
        } else {
            *(float4*)(out + (size_t)i * D + lane * 4) = make_float4(o[0], o[1], o[2], o[3]);
        }
    }
}

// ---------------- segment starts via binary search on sorted batch (int32) ----------------
__global__ void seg_start_kernel(const int* __restrict__ batch, int N, int G,
                                 int* __restrict__ start) {
    int g = blockIdx.x * blockDim.x + threadIdx.x;
    if (g > G) return;
    int lo = 0, hi = N;
    while (lo < hi) {
        int mid = (lo + hi) >> 1;
        if (batch[mid] < g) lo = mid + 1; else hi = mid;
    }
    start[g] = lo;
}

// ---------------- max pool per graph (+ sg_b folded in) ----------------
__global__ void pool_kernel(const float* __restrict__ z, const int* __restrict__ start,
                            const float* __restrict__ sgb, float* __restrict__ pooled) {
    int g = blockIdx.x;
    int j = threadIdx.x;  // 64
    int s = start[g], e = start[g + 1];
    float m = -3.4028235e38f;
    for (int i = s; i < e; i++) m = fmaxf(m, z[(size_t)i * 64 + j]);
    pooled[g * 64 + j] = m + sgb[j];
}

// ---------------- head MLP ----------------
__global__ void head_kernel(const float* __restrict__ pooled,
                            const float* __restrict__ fc1w, const float* __restrict__ fc1b,
                            const float* __restrict__ fc2w, const float* __restrict__ fc2b,
                            const float* __restrict__ cpdw, const float* __restrict__ cpdb,
                            const float* __restrict__ combw, const float* __restrict__ combb,
                            float* __restrict__ out, int G) {
    int g = blockIdx.x;
    int t = threadIdx.x;  // 64
    __shared__ float z0[64], z1[32], z2[16];
    z0[t] = pooled[g * 64 + t];
    __syncthreads();
    if (t < 32) {
        float s = fc1b[t];
        for (int k = 0; k < 64; k++) s = fmaf(z0[k], fc1w[k * 32 + t], s);
        z1[t] = fmaxf(s, 0.f);
    }
    __syncthreads();
    if (t < 16) {
        float s = fc2b[t];
        for (int k = 0; k < 32; k++) s = fmaf(z1[k], fc2w[k * 16 + t], s);
        z2[t] = fmaxf(s, 0.f);
    }
    __syncthreads();
    if (t == 0) {
        float s = cpdb[0];
        for (int k = 0; k < 16; k++) s = fmaf(z2[k], cpdw[k], s);
        out[g] = s;
    }
    if (t == 1) {
        float s = combb[0];
        for (int k = 0; k < 16; k++) s = fmaf(z2[k], combw[k], s);
        out[G + g] = s;
    }
}

// ---------------- host side ----------------
extern "C" void kernel_launch(void* const* d_in, const int* in_sizes, int n_in,
                              void* d_out, int out_size) {
    const float* x     = (const float*)d_in[0];
    const int*   ei    = (const int*)d_in[1];
    const int*   batch = (const int*)d_in[2];
    const float* enc_w1 = (const float*)d_in[3];
    const float* enc_b1 = (const float*)d_in[4];
    const float* enc_w2 = (const float*)d_in[5];
    const float* enc_b2 = (const float*)d_in[6];
    const float* w1 = (const float*)d_in[7];
    const float* b1 = (const float*)d_in[8];
    const float* w2 = (const float*)d_in[9];
    const float* b2 = (const float*)d_in[10];
    const float* w3 = (const float*)d_in[11];
    const float* b3 = (const float*)d_in[12];
    const float* sg_w = (const float*)d_in[13];
    const float* sg_b = (const float*)d_in[14];
    const float* fc1_w = (const float*)d_in[15];
    const float* fc1_b = (const float*)d_in[16];
    const float* fc2_w = (const float*)d_in[17];
    const float* fc2_b = (const float*)d_in[18];
    const float* cpd_w = (const float*)d_in[19];
    const float* cpd_b = (const float*)d_in[20];
    const float* comb_w = (const float*)d_in[21];
    const float* comb_b = (const float*)d_in[22];
    float* out = (float*)d_out;

    const int N = in_sizes[0] / 128;
    const int E = in_sizes[1] / 2;
    const int G = out_size / 2;

    const int* src = ei;
    const int* dst = ei + E;

    void *pT16, *pX16, *pY16, *pA, *pB, *pDeg, *pDinv, *pRp, *pTmp, *pSums, *pFill,
         *pPairs, *pStart, *pPool;
    cudaGetSymbolAddress(&pT16, g_h16T);
    cudaGetSymbolAddress(&pX16, g_h16X);
    cudaGetSymbolAddress(&pY16, g_h16Y);
    cudaGetSymbolAddress(&pA, g_bufA);
    cudaGetSymbolAddress(&pB, g_bufB);
    cudaGetSymbolAddress(&pDeg, g_deg);
    cudaGetSymbolAddress(&pDinv, g_dinv);
    cudaGetSymbolAddress(&pRp, g_rowptr);
    cudaGetSymbolAddress(&pTmp, g_tmp);
    cudaGetSymbolAddress(&pSums, g_sums);
    cudaGetSymbolAddress(&pFill, g_fill);
    cudaGetSymbolAddress(&pPairs, g_pairs);
    cudaGetSymbolAddress(&pStart, g_start);
    cudaGetSymbolAddress(&pPool, g_pooled);
    __half* T16 = (__half*)pT16;
    __half* X16 = (__half*)pX16;
    __half* Y16 = (__half*)pY16;
    float* bufA = (float*)pA;
    float* bufB = (float*)pB;
    float* deg = (float*)pDeg;
    float* dinv = (float*)pDinv;
    int* rp = (int*)pRp;
    int* tmp = (int*)pTmp;
    int* sums = (int*)pSums;
    int* fill = (int*)pFill;
    int2* pairs = (int2*)pPairs;
    int* start = (int*)pStart;
    float* pooled = (float*)pPool;

    const int TB = 256;
    const int nchunks = cdiv(N, 1024);

    // ---- degree / dinv ----
    deg_init_kernel<<<cdiv(N, TB), TB>>>(deg, fill, N);
    deg_accum_kernel<<<cdiv(E, TB), TB>>>(dst, deg, E);
    dinv_kernel<<<cdiv(N, TB), TB>>>(deg, dinv, N);

    // ---- CSR build (counting sort by dst) ----
    scan_chunk_kernel<<<nchunks, 1024>>>(deg, tmp, sums, N);
    scan_sums_kernel<<<1, 32>>>(sums, nchunks);
    finalize_rowptr_kernel<<<cdiv(N, TB), TB>>>(tmp, sums, rp, N, E);
    scatter_kernel<<<cdiv(E, TB), TB>>>(src, dst, dinv, rp, fill, pairs, E);

    const int gemmB = 128;
    const int gemmGrid = cdiv(N, 32);
    const int propGrid = cdiv(N, 8);  // warp per node, 8 warps/block

    // ---- encoder layer 1 ----
    gemm_kernel<128, 128, false, true><<<gemmGrid, gemmB>>>(x, enc_w1, T16, N);
    csr_prop16_kernel<128, false, false><<<propGrid, TB>>>(T16, bufA, pairs, rp, dinv, enc_b1, N);

    // ---- encoder layer 2 (relu fused into GEMM A-load) ----
    gemm_kernel<128, 64, true, true><<<gemmGrid, gemmB>>>(bufA, enc_w2, T16, N);
    csr_prop16_kernel<64, false, false><<<propGrid, TB>>>(T16, bufA, pairs, rp, dinv, enc_b2, N);

    // ---- conv1 (enc2 output NOT relu'd) ----
    gemm_kernel<64, 64, false, true><<<gemmGrid, gemmB>>>(bufA, w1, T16, N);
    csr_prop16_kernel<64, false, false><<<propGrid, TB>>>(T16, bufA, pairs, rp, dinv, b1, N);

    // ---- conv2 ----
    gemm_kernel<64, 64, true, true><<<gemmGrid, gemmB>>>(bufA, w2, T16, N);
    csr_prop16_kernel<64, false, false><<<propGrid, TB>>>(T16, bufA, pairs, rp, dinv, b2, N);

    // ---- conv3 (prop writes fp16, pre-relu; relu fused into SG prop1) ----
    gemm_kernel<64, 64, true, true><<<gemmGrid, gemmB>>>(bufA, w3, T16, N);
    csr_prop16_kernel<64, false, true><<<propGrid, TB>>>(T16, X16, pairs, rp, dinv, b3, N);

    // ---- SGConv: 4 propagations (all fp16 gather) ----
    csr_prop16_kernel<64, true, true><<<propGrid, TB>>>(X16, Y16, pairs, rp, dinv, nullptr, N);
    csr_prop16_kernel<64, false, true><<<propGrid, TB>>>(Y16, X16, pairs, rp, dinv, nullptr, N);
    csr_prop16_kernel<64, false, true><<<propGrid, TB>>>(X16, Y16, pairs, rp, dinv, nullptr, N);
    csr_prop16_kernel<64, false, false><<<propGrid, TB>>>(Y16, bufA, pairs, rp, dinv, nullptr, N);

    // ---- SG linear (bias folded past max-pool) ----
    gemm_kernel<64, 64, false, false><<<gemmGrid, gemmB>>>(bufA, sg_w, bufB, N);

    // ---- pool + head ----
    seg_start_kernel<<<cdiv(G + 1, TB), TB>>>(batch, N, G, start);
    pool_kernel<<<G, 64>>>(bufB, start, sg_b, pooled);
    head_kernel<<<G, 64>>>(pooled, fc1_w, fc1_b, fc2_w, fc2_b,
                           cpd_w, cpd_b, comb_w, comb_b, out, G);
}

// round 6
// speedup vs baseline: 2.6109x; 1.0048x over previous
#include <cuda_runtime.h>
#include <cuda_fp16.h>
#include <cstdint>

// ---------------- static scratch (no allocations allowed) ----------------
#define MAXN 100000
#define MAXE 3200000
#define MAXG 256

__device__ __half g_h16T[(size_t)MAXN * 128];  // gathered GEMM outputs (fp16)
__device__ __half g_h16X[(size_t)MAXN * 64];   // SG chain ping
__device__ __half g_h16Y[(size_t)MAXN * 64];   // SG chain pong
__device__ float  g_bufA[(size_t)MAXN * 128];  // prop outputs (fp32, read linearly)
__device__ float  g_bufB[(size_t)MAXN * 64];   // SG linear out (fp32, pooled)
__device__ float  g_deg[MAXN];
__device__ float  g_dinv[MAXN];
__device__ int    g_rowptr[MAXN + 1];
__device__ int    g_tmp[MAXN];
__device__ int    g_sums[256];
__device__ int    g_fill[MAXN];
__device__ int2   g_pairs[MAXE];  // (src, norm-as-int)
__device__ int    g_start[MAXG + 1];
__device__ float  g_pooled[MAXG * 64];

static inline int cdiv(long long a, int b) { return (int)((a + b - 1) / b); }

// ---------------- degree / norm prep ----------------
__global__ void deg_init_kernel(float* __restrict__ deg, int* __restrict__ fill, int N) {
    int i = blockIdx.x * blockDim.x + threadIdx.x;
    if (i < N) { deg[i] = 1.0f; fill[i] = 0; }  // self loop
}

__global__ void deg_accum_kernel(const int* __restrict__ dst, float* __restrict__ deg, int E) {
    int e = blockIdx.x * blockDim.x + threadIdx.x;
    if (e < E) atomicAdd(&deg[dst[e]], 1.0f);
}

__global__ void dinv_kernel(const float* __restrict__ deg, float* __restrict__ dinv, int N) {
    int i = blockIdx.x * blockDim.x + threadIdx.x;
    if (i < N) dinv[i] = rsqrtf(deg[i]);
}

// ---------------- CSR build: scan of in-degree (excl self loops) ----------------
__global__ void scan_chunk_kernel(const float* __restrict__ deg, int* __restrict__ excl,
                                  int* __restrict__ sums, int N) {
    __shared__ int sh[1024];
    int i = blockIdx.x * 1024 + threadIdx.x;
    int v = 0;
    if (i < N) v = (int)deg[i] - 1;
    sh[threadIdx.x] = v;
    __syncthreads();
    for (int off = 1; off < 1024; off <<= 1) {
        int add = (threadIdx.x >= off) ? sh[threadIdx.x - off] : 0;
        __syncthreads();
        sh[threadIdx.x] += add;
        __syncthreads();
    }
    if (i < N) excl[i] = sh[threadIdx.x] - v;
    if (threadIdx.x == 1023) sums[blockIdx.x] = sh[1023];
}

__global__ void scan_sums_kernel(int* __restrict__ sums, int nchunks) {
    if (threadIdx.x == 0 && blockIdx.x == 0) {
        int run = 0;
        for (int c = 0; c < nchunks; c++) {
            int v = sums[c];
            sums[c] = run;
            run += v;
        }
    }
}

__global__ void finalize_rowptr_kernel(const int* __restrict__ excl, const int* __restrict__ sums,
                                       int* __restrict__ rp, int N, int E) {
    int i = blockIdx.x * blockDim.x + threadIdx.x;
    if (i < N) rp[i] = excl[i] + sums[i >> 10];
    if (i == 0) rp[N] = E;
}

__global__ void scatter_kernel(const int* __restrict__ src, const int* __restrict__ dst,
                               const float* __restrict__ dinv, const int* __restrict__ rp,
                               int* __restrict__ fill, int2* __restrict__ pairs, int E) {
    int e = blockIdx.x * blockDim.x + threadIdx.x;
    if (e >= E) return;
    int s = src[e];
    int d = dst[e];
    int pos = rp[d] + atomicAdd(&fill[d], 1);
    pairs[pos] = make_int2(s, __float_as_int(dinv[s] * dinv[d]));
}

// ---------------- GEMM: OUT[N,DOUT] = act(A)[N,DIN] @ W[DIN,DOUT], fp32 math ----------------
template <int DIN, int DOUT, bool RELU_IN, bool OUT_HALF>
__global__ void gemm_kernel(const float* __restrict__ A, const float* __restrict__ W,
                            void* __restrict__ outv, int N) {
    constexpr int TR = 32;
    constexpr int KC = 32;
    constexpr int CT = DOUT / 32;  // 4 or 2
    __shared__ float As[TR][KC + 1];
    __shared__ float Ws[KC][DOUT];
    const int tid = threadIdx.x;  // 128
    const int tx = tid & 31;
    const int ty = tid >> 5;
    const int rbase = blockIdx.x * TR;

    float acc[8][CT];
#pragma unroll
    for (int i = 0; i < 8; i++)
#pragma unroll
        for (int j = 0; j < CT; j++) acc[i][j] = 0.f;

    for (int k0 = 0; k0 < DIN; k0 += KC) {
#pragma unroll
        for (int it = 0; it < 2; it++) {
            int r = (tid >> 3) + it * 16;
            int c = (tid & 7) * 4;
            float4 v = make_float4(0.f, 0.f, 0.f, 0.f);
            int gr = rbase + r;
            if (gr < N) v = *(const float4*)(A + (size_t)gr * DIN + k0 + c);
            if (RELU_IN) {
                v.x = fmaxf(v.x, 0.f); v.y = fmaxf(v.y, 0.f);
                v.z = fmaxf(v.z, 0.f); v.w = fmaxf(v.w, 0.f);
            }
            As[r][c + 0] = v.x; As[r][c + 1] = v.y;
            As[r][c + 2] = v.z; As[r][c + 3] = v.w;
        }
        constexpr int WLOOP = (KC * DOUT) / (128 * 4);
#pragma unroll
        for (int it = 0; it < WLOOP; it++) {
            int idx = (it * 128 + tid) * 4;
            int kk = idx / DOUT;
            int c = idx % DOUT;
            *(float4*)(&Ws[kk][c]) = *(const float4*)(W + (size_t)(k0 + kk) * DOUT + c);
        }
        __syncthreads();
#pragma unroll
        for (int kk = 0; kk < KC; kk++) {
            float wv[CT];
#pragma unroll
            for (int j = 0; j < CT; j++) wv[j] = Ws[kk][tx * CT + j];
#pragma unroll
            for (int rr = 0; rr < 8; rr++) {
                float a = As[ty * 8 + rr][kk];
#pragma unroll
                for (int j = 0; j < CT; j++) acc[rr][j] = fmaf(a, wv[j], acc[rr][j]);
            }
        }
        __syncthreads();
    }
#pragma unroll
    for (int rr = 0; rr < 8; rr++) {
        int gr = rbase + ty * 8 + rr;
        if (gr >= N) continue;
        if constexpr (OUT_HALF) {
            __half* out = (__half*)outv;
            __half2* p = (__half2*)(out + (size_t)gr * DOUT + tx * CT);
#pragma unroll
            for (int j = 0; j < CT / 2; j++)
                p[j] = __floats2half2_rn(acc[rr][2 * j], acc[rr][2 * j + 1]);
        } else {
            float* out = (float*)outv;
            if constexpr (CT == 4) {
                *(float4*)(out + (size_t)gr * DOUT + tx * 4) =
                    make_float4(acc[rr][0], acc[rr][1], acc[rr][2], acc[rr][3]);
            } else {
                *(float2*)(out + (size_t)gr * DOUT + tx * 2) =
                    make_float2(acc[rr][0], acc[rr][1]);
            }
        }
    }
}

// ---------------- CSR propagate, fp16 gather / fp32 accumulate, 8-deep MLP ----------------
// out[i] = dinv[i]^2 * act(t[i]) + bias + sum_j norm_j * act(t[src_j])
template <int D, bool RELU, bool OUT_HALF>
__global__ void csr_prop16_kernel(const __half* __restrict__ t, void* __restrict__ outv,
                                  const int2* __restrict__ pairs, const int* __restrict__ rp,
                                  const float* __restrict__ dinv, const float* __restrict__ bias,
                                  int N) {
    constexpr int H = D / 32;  // halves per lane: 2 (D=64) or 4 (D=128)
    int warp = (blockIdx.x * blockDim.x + threadIdx.x) >> 5;
    int lane = threadIdx.x & 31;
    if (warp >= N) return;
    const int i = warp;
    int j0 = rp[i], j1 = rp[i + 1];

    float acc[H];
#pragma unroll
    for (int v = 0; v < H; v++) acc[v] = 0.f;

    auto load_row = [&](int s, float* f) {
        if constexpr (H == 2) {
            unsigned u = *((const unsigned*)(t + (size_t)s * D) + lane);
            __half2 h = *(__half2*)&u;
            float2 fv = __half22float2(h);
            f[0] = fv.x; f[1] = fv.y;
        } else {
            uint2 u = *((const uint2*)(t + (size_t)s * D) + lane);
            __half2 ha = *(__half2*)&u.x;
            __half2 hb = *(__half2*)&u.y;
            float2 fa = __half22float2(ha);
            float2 fb = __half22float2(hb);
            f[0] = fa.x; f[1] = fa.y; f[2] = fb.x; f[3] = fb.y;
        }
    };

    int j = j0;
    // 8-deep pipelined main loop: 8 independent pair loads, then 8 independent
    // row gathers in flight, then 8 FMAs. MLP ~8 vs the old ~2.
    for (; j + 7 < j1; j += 8) {
        int2 p[8];
#pragma unroll
        for (int u = 0; u < 8; u++) p[u] = pairs[j + u];
        float a[8][H > 2 ? 4 : 2];
#pragma unroll
        for (int u = 0; u < 8; u++) load_row(p[u].x, a[u]);
#pragma unroll
        for (int u = 0; u < 8; u++) {
            float w = __int_as_float(p[u].y);
#pragma unroll
            for (int v = 0; v < H; v++) {
                float xv = RELU ? fmaxf(a[u][v], 0.f) : a[u][v];
                acc[v] = fmaf(w, xv, acc[v]);
            }
        }
    }
    for (; j + 1 < j1; j += 2) {
        int2 p0 = pairs[j];
        int2 p1 = pairs[j + 1];
        float a0[H], a1[H];
        load_row(p0.x, a0);
        load_row(p1.x, a1);
        float w0 = __int_as_float(p0.y);
        float w1 = __int_as_float(p1.y);
#pragma unroll
        for (int v = 0; v < H; v++) {
            float x0 = RELU ? fmaxf(a0[v], 0.f) : a0[v];
            float x1 = RELU ? fmaxf(a1[v], 0.f) : a1[v];
            acc[v] = fmaf(w0, x0, acc[v]);
            acc[v] = fmaf(w1, x1, acc[v]);
        }
    }
    if (j < j1) {
        int2 p0 = pairs[j];
        float w0 = __int_as_float(p0.y);
        float a0[H];
        load_row(p0.x, a0);
#pragma unroll
        for (int v = 0; v < H; v++) {
            float x0 = RELU ? fmaxf(a0[v], 0.f) : a0[v];
            acc[v] = fmaf(w0, x0, acc[v]);
        }
    }

    float dv = dinv[i];
    float sc = dv * dv;
    float self[H];
    load_row(i, self);
    float o[H];
#pragma unroll
    for (int v = 0; v < H; v++) {
        float sv = RELU ? fmaxf(self[v], 0.f) : self[v];
        float b = bias ? bias[lane * H + v] : 0.f;
        o[v] = fmaf(sc, sv, acc[v]) + b;
    }

    if constexpr (OUT_HALF) {
        __half* out = (__half*)outv;
        if constexpr (H == 2) {
            __half2 h = __floats2half2_rn(o[0], o[1]);
            *((unsigned*)(out + (size_t)i * D) + lane) = *(unsigned*)&h;
        } else {
            __half2 ha = __floats2half2_rn(o[0], o[1]);
            __half2 hb = __floats2half2_rn(o[2], o[3]);
            uint2 u;
            u.x = *(unsigned*)&ha;
            u.y = *(unsigned*)&hb;
            *((uint2*)(out + (size_t)i * D) + lane) = u;
        }
    } else {
        float* out = (float*)outv;
        if constexpr (H == 2) {
            *(float2*)(out + (size_t)i * D + lane * 2) = make_float2(o[0], o[1]);
        } else {
            *(float4*)(out + (size_t)i * D + lane * 4) = make_float4(o[0], o[1], o[2], o[3]);
        }
    }
}

// ---------------- segment starts via binary search on sorted batch (int32) ----------------
__global__ void seg_start_kernel(const int* __restrict__ batch, int N, int G,
                                 int* __restrict__ start) {
    int g = blockIdx.x * blockDim.x + threadIdx.x;
    if (g > G) return;
    int lo = 0, hi = N;
    while (lo < hi) {
        int mid = (lo + hi) >> 1;
        if (batch[mid] < g) lo = mid + 1; else hi = mid;
    }
    start[g] = lo;
}

// ---------------- max pool per graph (+ sg_b folded in) ----------------
__global__ void pool_kernel(const float* __restrict__ z, const int* __restrict__ start,
                            const float* __restrict__ sgb, float* __restrict__ pooled) {
    int g = blockIdx.x;
    int j = threadIdx.x;  // 64
    int s = start[g], e = start[g + 1];
    float m = -3.4028235e38f;
    for (int i = s; i < e; i++) m = fmaxf(m, z[(size_t)i * 64 + j]);
    pooled[g * 64 + j] = m + sgb[j];
}

// ---------------- head MLP ----------------
__global__ void head_kernel(const float* __restrict__ pooled,
                            const float* __restrict__ fc1w, const float* __restrict__ fc1b,
                            const float* __restrict__ fc2w, const float* __restrict__ fc2b,
                            const float* __restrict__ cpdw, const float* __restrict__ cpdb,
                            const float* __restrict__ combw, const float* __restrict__ combb,
                            float* __restrict__ out, int G) {
    int g = blockIdx.x;
    int t = threadIdx.x;  // 64
    __shared__ float z0[64], z1[32], z2[16];
    z0[t] = pooled[g * 64 + t];
    __syncthreads();
    if (t < 32) {
        float s = fc1b[t];
        for (int k = 0; k < 64; k++) s = fmaf(z0[k], fc1w[k * 32 + t], s);
        z1[t] = fmaxf(s, 0.f);
    }
    __syncthreads();
    if (t < 16) {
        float s = fc2b[t];
        for (int k = 0; k < 32; k++) s = fmaf(z1[k], fc2w[k * 16 + t], s);
        z2[t] = fmaxf(s, 0.f);
    }
    __syncthreads();
    if (t == 0) {
        float s = cpdb[0];
        for (int k = 0; k < 16; k++) s = fmaf(z2[k], cpdw[k], s);
        out[g] = s;
    }
    if (t == 1) {
        float s = combb[0];
        for (int k = 0; k < 16; k++) s = fmaf(z2[k], combw[k], s);
        out[G + g] = s;
    }
}

// ---------------- host side ----------------
extern "C" void kernel_launch(void* const* d_in, const int* in_sizes, int n_in,
                              void* d_out, int out_size) {
    const float* x     = (const float*)d_in[0];
    const int*   ei    = (const int*)d_in[1];
    const int*   batch = (const int*)d_in[2];
    const float* enc_w1 = (const float*)d_in[3];
    const float* enc_b1 = (const float*)d_in[4];
    const float* enc_w2 = (const float*)d_in[5];
    const float* enc_b2 = (const float*)d_in[6];
    const float* w1 = (const float*)d_in[7];
    const float* b1 = (const float*)d_in[8];
    const float* w2 = (const float*)d_in[9];
    const float* b2 = (const float*)d_in[10];
    const float* w3 = (const float*)d_in[11];
    const float* b3 = (const float*)d_in[12];
    const float* sg_w = (const float*)d_in[13];
    const float* sg_b = (const float*)d_in[14];
    const float* fc1_w = (const float*)d_in[15];
    const float* fc1_b = (const float*)d_in[16];
    const float* fc2_w = (const float*)d_in[17];
    const float* fc2_b = (const float*)d_in[18];
    const float* cpd_w = (const float*)d_in[19];
    const float* cpd_b = (const float*)d_in[20];
    const float* comb_w = (const float*)d_in[21];
    const float* comb_b = (const float*)d_in[22];
    float* out = (float*)d_out;

    const int N = in_sizes[0] / 128;
    const int E = in_sizes[1] / 2;
    const int G = out_size / 2;

    const int* src = ei;
    const int* dst = ei + E;

    void *pT16, *pX16, *pY16, *pA, *pB, *pDeg, *pDinv, *pRp, *pTmp, *pSums, *pFill,
         *pPairs, *pStart, *pPool;
    cudaGetSymbolAddress(&pT16, g_h16T);
    cudaGetSymbolAddress(&pX16, g_h16X);
    cudaGetSymbolAddress(&pY16, g_h16Y);
    cudaGetSymbolAddress(&pA, g_bufA);
    cudaGetSymbolAddress(&pB, g_bufB);
    cudaGetSymbolAddress(&pDeg, g_deg);
    cudaGetSymbolAddress(&pDinv, g_dinv);
    cudaGetSymbolAddress(&pRp, g_rowptr);
    cudaGetSymbolAddress(&pTmp, g_tmp);
    cudaGetSymbolAddress(&pSums, g_sums);
    cudaGetSymbolAddress(&pFill, g_fill);
    cudaGetSymbolAddress(&pPairs, g_pairs);
    cudaGetSymbolAddress(&pStart, g_start);
    cudaGetSymbolAddress(&pPool, g_pooled);
    __half* T16 = (__half*)pT16;
    __half* X16 = (__half*)pX16;
    __half* Y16 = (__half*)pY16;
    float* bufA = (float*)pA;
    float* bufB = (float*)pB;
    float* deg = (float*)pDeg;
    float* dinv = (float*)pDinv;
    int* rp = (int*)pRp;
    int* tmp = (int*)pTmp;
    int* sums = (int*)pSums;
    int* fill = (int*)pFill;
    int2* pairs = (int2*)pPairs;
    int* start = (int*)pStart;
    float* pooled = (float*)pPool;

    const int TB = 256;
    const int nchunks = cdiv(N, 1024);

    // ---- degree / dinv ----
    deg_init_kernel<<<cdiv(N, TB), TB>>>(deg, fill, N);
    deg_accum_kernel<<<cdiv(E, TB), TB>>>(dst, deg, E);
    dinv_kernel<<<cdiv(N, TB), TB>>>(deg, dinv, N);

    // ---- CSR build (counting sort by dst) ----
    scan_chunk_kernel<<<nchunks, 1024>>>(deg, tmp, sums, N);
    scan_sums_kernel<<<1, 32>>>(sums, nchunks);
    finalize_rowptr_kernel<<<cdiv(N, TB), TB>>>(tmp, sums, rp, N, E);
    scatter_kernel<<<cdiv(E, TB), TB>>>(src, dst, dinv, rp, fill, pairs, E);

    const int gemmB = 128;
    const int gemmGrid = cdiv(N, 32);
    const int propGrid = cdiv(N, 8);  // warp per node, 8 warps/block

    // ---- encoder layer 1 ----
    gemm_kernel<128, 128, false, true><<<gemmGrid, gemmB>>>(x, enc_w1, T16, N);
    csr_prop16_kernel<128, false, false><<<propGrid, TB>>>(T16, bufA, pairs, rp, dinv, enc_b1, N);

    // ---- encoder layer 2 (relu fused into GEMM A-load) ----
    gemm_kernel<128, 64, true, true><<<gemmGrid, gemmB>>>(bufA, enc_w2, T16, N);
    csr_prop16_kernel<64, false, false><<<propGrid, TB>>>(T16, bufA, pairs, rp, dinv, enc_b2, N);

    // ---- conv1 (enc2 output NOT relu'd) ----
    gemm_kernel<64, 64, false, true><<<gemmGrid, gemmB>>>(bufA, w1, T16, N);
    csr_prop16_kernel<64, false, false><<<propGrid, TB>>>(T16, bufA, pairs, rp, dinv, b1, N);

    // ---- conv2 ----
    gemm_kernel<64, 64, true, true><<<gemmGrid, gemmB>>>(bufA, w2, T16, N);
    csr_prop16_kernel<64, false, false><<<propGrid, TB>>>(T16, bufA, pairs, rp, dinv, b2, N);

    // ---- conv3 (prop writes fp16, pre-relu; relu fused into SG prop1) ----
    gemm_kernel<64, 64, true, true><<<gemmGrid, gemmB>>>(bufA, w3, T16, N);
    csr_prop16_kernel<64, false, true><<<propGrid, TB>>>(T16, X16, pairs, rp, dinv, b3, N);

    // ---- SGConv: 4 propagations (all fp16 gather) ----
    csr_prop16_kernel<64, true, true><<<propGrid, TB>>>(X16, Y16, pairs, rp, dinv, nullptr, N);
    csr_prop16_kernel<64, false, true><<<propGrid, TB>>>(Y16, X16, pairs, rp, dinv, nullptr, N);
    csr_prop16_kernel<64, false, true><<<propGrid, TB>>>(X16, Y16, pairs, rp, dinv, nullptr, N);
    csr_prop16_kernel<64, false, false><<<propGrid, TB>>>(Y16, bufA, pairs, rp, dinv, nullptr, N);

    // ---- SG linear (bias folded past max-pool) ----
    gemm_kernel<64, 64, false, false><<<gemmGrid, gemmB>>>(bufA, sg_w, bufB, N);

    // ---- pool + head ----
    seg_start_kernel<<<cdiv(G + 1, TB), TB>>>(batch, N, G, start);
    pool_kernel<<<G, 64>>>(bufB, start, sg_b, pooled);
    head_kernel<<<G, 64>>>(pooled, fc1_w, fc1_b, fc2_w, fc2_b,
                           cpd_w, cpd_b, comb_w, comb_b, out, G);
}